// round 1
// baseline (speedup 1.0000x reference)
#include <cuda_runtime.h>
#include <math.h>

#define NROWS 131072
#define RB    (NROWS/64)   // 2048 row-blocks

// ---------------- scratch (device globals; no allocation allowed) ----------------
__device__ float g_bufA[(size_t)NROWS * 512];
__device__ float g_bufB[(size_t)NROWS * 512];
__device__ float g_z   [(size_t)NROWS * 256];
__device__ float g_q   [(size_t)NROWS * 256];
__device__ float g_cn  [2 * 1024];
__device__ float g_l1p [RB];
__device__ float g_vqp [RB];

// ---------------- generic fp32 SGEMM: C[N,M] = A[N,K] @ B[K,M] + bias ----------------
// 64x64 block tile, BK=16, 256 threads, 4x4 per thread.
// L1EPI: instead of storing C, accumulate sum |Xref - out| into part[blockIdx.x].
template<int RELU, int L1EPI>
__global__ __launch_bounds__(256) void sgemm_k(
    const float* __restrict__ A, const float* __restrict__ B,
    const float* __restrict__ bias, float* __restrict__ C,
    int K, int M, const float* __restrict__ Xref, float* __restrict__ part)
{
    __shared__ float As[64][17];
    __shared__ __align__(16) float Bs[16][64];

    const int tid = threadIdx.x;
    const int tx = tid & 15, ty = tid >> 4;
    const int row0 = blockIdx.x * 64;
    const int col0 = blockIdx.y * 64;

    float acc[4][4] = {};

    for (int k0 = 0; k0 < K; k0 += 16) {
        // A tile: rows ty+16i, k = tx (coalesced along k)
        #pragma unroll
        for (int i = 0; i < 4; i++) {
            int r  = ty + 16 * i;
            int kk = k0 + tx;
            As[r][tx] = (kk < K) ? A[(size_t)(row0 + r) * K + kk] : 0.0f;
        }
        // B tile: k = ty, 4 cols starting at 4*tx
        {
            int kk = k0 + ty;
            int c  = col0 + 4 * tx;
            float4 v = make_float4(0.f, 0.f, 0.f, 0.f);
            if (kk < K) {
                if (c + 3 < M) {
                    v = *(const float4*)(B + (size_t)kk * M + c);
                } else {
                    float t0 = (c + 0 < M) ? B[(size_t)kk * M + c + 0] : 0.f;
                    float t1 = (c + 1 < M) ? B[(size_t)kk * M + c + 1] : 0.f;
                    float t2 = (c + 2 < M) ? B[(size_t)kk * M + c + 2] : 0.f;
                    float t3 = (c + 3 < M) ? B[(size_t)kk * M + c + 3] : 0.f;
                    v = make_float4(t0, t1, t2, t3);
                }
            }
            *(float4*)(&Bs[ty][4 * tx]) = v;
        }
        __syncthreads();

        #pragma unroll
        for (int k = 0; k < 16; k++) {
            float4 b = *(const float4*)(&Bs[k][4 * tx]);
            float a0 = As[4 * ty + 0][k];
            float a1 = As[4 * ty + 1][k];
            float a2 = As[4 * ty + 2][k];
            float a3 = As[4 * ty + 3][k];
            acc[0][0] = fmaf(a0, b.x, acc[0][0]); acc[0][1] = fmaf(a0, b.y, acc[0][1]);
            acc[0][2] = fmaf(a0, b.z, acc[0][2]); acc[0][3] = fmaf(a0, b.w, acc[0][3]);
            acc[1][0] = fmaf(a1, b.x, acc[1][0]); acc[1][1] = fmaf(a1, b.y, acc[1][1]);
            acc[1][2] = fmaf(a1, b.z, acc[1][2]); acc[1][3] = fmaf(a1, b.w, acc[1][3]);
            acc[2][0] = fmaf(a2, b.x, acc[2][0]); acc[2][1] = fmaf(a2, b.y, acc[2][1]);
            acc[2][2] = fmaf(a2, b.z, acc[2][2]); acc[2][3] = fmaf(a2, b.w, acc[2][3]);
            acc[3][0] = fmaf(a3, b.x, acc[3][0]); acc[3][1] = fmaf(a3, b.y, acc[3][1]);
            acc[3][2] = fmaf(a3, b.z, acc[3][2]); acc[3][3] = fmaf(a3, b.w, acc[3][3]);
        }
        __syncthreads();
    }

    if (!L1EPI) {
        #pragma unroll
        for (int i = 0; i < 4; i++) {
            int r = row0 + 4 * ty + i;
            int c = col0 + 4 * tx;
            float4 o;
            o.x = acc[i][0] + bias[c + 0];
            o.y = acc[i][1] + bias[c + 1];
            o.z = acc[i][2] + bias[c + 2];
            o.w = acc[i][3] + bias[c + 3];
            if (RELU) {
                o.x = fmaxf(o.x, 0.f); o.y = fmaxf(o.y, 0.f);
                o.z = fmaxf(o.z, 0.f); o.w = fmaxf(o.w, 0.f);
            }
            *(float4*)(C + (size_t)r * M + c) = o;  // M % 64 == 0 on this path
        }
    } else {
        float s = 0.f;
        #pragma unroll
        for (int i = 0; i < 4; i++) {
            int r = row0 + 4 * ty + i;
            #pragma unroll
            for (int j = 0; j < 4; j++) {
                int c = col0 + 4 * tx + j;
                if (c < M) {
                    float v = acc[i][j] + bias[c];
                    s += fabsf(Xref[(size_t)r * M + c] - v);
                }
            }
        }
        __shared__ float red[256];
        red[tid] = s;
        __syncthreads();
        #pragma unroll
        for (int off = 128; off > 0; off >>= 1) {
            if (tid < off) red[tid] += red[tid + off];
            __syncthreads();
        }
        if (tid == 0) part[blockIdx.x] = red[0];
    }
}

// ---------------- codebook half-norms: cn[q*1024+c] = 0.5 * ||cb[q][c]||^2 ----------------
__global__ __launch_bounds__(256) void cn_k(const float* __restrict__ cb, float* __restrict__ cn)
{
    int w = (blockIdx.x * blockDim.x + threadIdx.x) >> 5;  // warp id = code id
    int lane = threadIdx.x & 31;
    if (w < 2048) {
        const float* c = cb + (size_t)w * 256;
        float s = 0.f;
        #pragma unroll
        for (int k = lane; k < 256; k += 32) s = fmaf(c[k], c[k], s);
        #pragma unroll
        for (int off = 16; off > 0; off >>= 1) s += __shfl_xor_sync(0xffffffff, s, off);
        if (lane == 0) cn[w] = 0.5f * s;
    }
}

// ---------------- fused residual-VQ kernel ----------------
// 64 rows per block; z tile lives in smem, updated in place to the residual.
// argmin over (0.5||c||^2 - r.c) == argmin squared distance; tie-break = lowest index
// (matches jnp.argmin first-occurrence).
struct VqSmem {
    float Z[64][260];     // z tile / residual (padded rows)
    float Bs[16][68];     // code tile, transposed [feat][code]
    float rb[64][17];     // per-row partial mins
    int   ri[64][17];
    int   ridx[64];
    float red[256];
};

__global__ __launch_bounds__(256) void vq_k(
    const float* __restrict__ zg, const float* __restrict__ cb,
    const float* __restrict__ cn, float* __restrict__ qsum,
    float* __restrict__ codes_out, float* __restrict__ vqpart)
{
    extern __shared__ __align__(16) char smem_raw[];
    VqSmem* S = (VqSmem*)smem_raw;

    const int tid = threadIdx.x;
    const int tx = tid & 15, ty = tid >> 4;
    const size_t row0 = (size_t)blockIdx.x * 64;

    // load z tile (64 x 256)
    #pragma unroll
    for (int i = 0; i < 16; i++) {
        int e = tid + 256 * i;
        int r = e >> 6, c4 = e & 63;
        *(float4*)(&S->Z[r][4 * c4]) = *(const float4*)(zg + (row0 + r) * 256 + 4 * c4);
    }
    __syncthreads();

    float vq_acc = 0.f;

    for (int q = 0; q < 2; q++) {
        const float* cbq = cb + (size_t)q * 1024 * 256;
        const float* cnq = cn + q * 1024;

        float best[4] = {1e30f, 1e30f, 1e30f, 1e30f};
        int   bidx[4] = {0, 0, 0, 0};

        for (int t = 0; t < 16; t++) {              // 64-code tiles
            const int c0 = t * 64;
            float acc[4][4] = {};
            for (int kk0 = 0; kk0 < 256; kk0 += 16) {
                // transpose-load code tile: Bs[feat][code]
                int crow = tid >> 2;     // code 0..63
                int kc   = tid & 3;      // feat group
                float4 v = *(const float4*)(cbq + (size_t)(c0 + crow) * 256 + kk0 + 4 * kc);
                S->Bs[4 * kc + 0][crow] = v.x;
                S->Bs[4 * kc + 1][crow] = v.y;
                S->Bs[4 * kc + 2][crow] = v.z;
                S->Bs[4 * kc + 3][crow] = v.w;
                __syncthreads();
                #pragma unroll
                for (int k = 0; k < 16; k++) {
                    float4 b = *(const float4*)(&S->Bs[k][4 * tx]);
                    float a0 = S->Z[4 * ty + 0][kk0 + k];
                    float a1 = S->Z[4 * ty + 1][kk0 + k];
                    float a2 = S->Z[4 * ty + 2][kk0 + k];
                    float a3 = S->Z[4 * ty + 3][kk0 + k];
                    acc[0][0] = fmaf(a0, b.x, acc[0][0]); acc[0][1] = fmaf(a0, b.y, acc[0][1]);
                    acc[0][2] = fmaf(a0, b.z, acc[0][2]); acc[0][3] = fmaf(a0, b.w, acc[0][3]);
                    acc[1][0] = fmaf(a1, b.x, acc[1][0]); acc[1][1] = fmaf(a1, b.y, acc[1][1]);
                    acc[1][2] = fmaf(a1, b.z, acc[1][2]); acc[1][3] = fmaf(a1, b.w, acc[1][3]);
                    acc[2][0] = fmaf(a2, b.x, acc[2][0]); acc[2][1] = fmaf(a2, b.y, acc[2][1]);
                    acc[2][2] = fmaf(a2, b.z, acc[2][2]); acc[2][3] = fmaf(a2, b.w, acc[2][3]);
                    acc[3][0] = fmaf(a3, b.x, acc[3][0]); acc[3][1] = fmaf(a3, b.y, acc[3][1]);
                    acc[3][2] = fmaf(a3, b.z, acc[3][2]); acc[3][3] = fmaf(a3, b.w, acc[3][3]);
                }
                __syncthreads();
            }
            // score epilogue: s = 0.5||c||^2 - r.c ; running argmin
            #pragma unroll
            for (int j = 0; j < 4; j++) {
                int code = c0 + 4 * tx + j;
                float cv = cnq[code];
                #pragma unroll
                for (int i = 0; i < 4; i++) {
                    float sd = cv - acc[i][j];
                    if (sd < best[i]) { best[i] = sd; bidx[i] = code; }
                }
            }
        }

        // cross-thread per-row argmin reduce (tie -> smallest index)
        #pragma unroll
        for (int i = 0; i < 4; i++) {
            S->rb[4 * ty + i][tx] = best[i];
            S->ri[4 * ty + i][tx] = bidx[i];
        }
        __syncthreads();
        if (tid < 64) {
            float bv = S->rb[tid][0]; int bi = S->ri[tid][0];
            #pragma unroll
            for (int u = 1; u < 16; u++) {
                float v = S->rb[tid][u]; int id = S->ri[tid][u];
                if (v < bv || (v == bv && id < bi)) { bv = v; bi = id; }
            }
            S->ridx[tid] = bi;
            codes_out[(row0 + tid) * 2 + q] = (float)bi;
        }
        __syncthreads();

        // gather code row, commitment loss term, in-place residual, accumulate qsum
        #pragma unroll
        for (int i = 0; i < 16; i++) {
            int e = tid + 256 * i;
            int r = e >> 6, c4 = e & 63;
            int code = S->ridx[r];
            float4 cv = *(const float4*)(cbq + (size_t)code * 256 + 4 * c4);
            float4 zv = *(float4*)(&S->Z[r][4 * c4]);
            float4 dv = make_float4(zv.x - cv.x, zv.y - cv.y, zv.z - cv.z, zv.w - cv.w);
            vq_acc += dv.x * dv.x + dv.y * dv.y + dv.z * dv.z + dv.w * dv.w;
            *(float4*)(&S->Z[r][4 * c4]) = dv;   // residual
            float* qp = qsum + (row0 + r) * 256 + 4 * c4;
            if (q == 0) {
                *(float4*)qp = cv;
            } else {
                float4 o = *(float4*)qp;
                o.x += cv.x; o.y += cv.y; o.z += cv.z; o.w += cv.w;
                *(float4*)qp = o;
            }
        }
        __syncthreads();
    }

    S->red[tid] = vq_acc;
    __syncthreads();
    #pragma unroll
    for (int off = 128; off > 0; off >>= 1) {
        if (tid < off) S->red[tid] += S->red[tid + off];
        __syncthreads();
    }
    if (tid == 0) vqpart[blockIdx.x] = S->red[0];
}

// ---------------- final deterministic loss combine ----------------
__global__ __launch_bounds__(256) void final_k(
    const float* __restrict__ l1p, const float* __restrict__ vqp, float* __restrict__ out)
{
    __shared__ float sa[256], sb[256];
    float a = 0.f, b = 0.f;
    for (int i = threadIdx.x; i < RB; i += 256) { a += l1p[i]; b += vqp[i]; }
    sa[threadIdx.x] = a; sb[threadIdx.x] = b;
    __syncthreads();
    #pragma unroll
    for (int off = 128; off > 0; off >>= 1) {
        if (threadIdx.x < off) {
            sa[threadIdx.x] += sa[threadIdx.x + off];
            sb[threadIdx.x] += sb[threadIdx.x + off];
        }
        __syncthreads();
    }
    if (threadIdx.x == 0) {
        float enc_loss = sa[0] / (131072.0f * 56.0f);
        float vq_loss  = sb[0] / (131072.0f * 256.0f);
        out[0] = enc_loss + 5.0f * vq_loss;
    }
}

// ---------------- launch ----------------
extern "C" void kernel_launch(void* const* d_in, const int* in_sizes, int n_in,
                              void* d_out, int out_size)
{
    const float* state = (const float*)d_in[0];
    const float* ew1 = (const float*)d_in[1];
    const float* eb1 = (const float*)d_in[2];
    const float* ew2 = (const float*)d_in[3];
    const float* eb2 = (const float*)d_in[4];
    const float* ew3 = (const float*)d_in[5];
    const float* eb3 = (const float*)d_in[6];
    const float* dw1 = (const float*)d_in[7];
    const float* db1 = (const float*)d_in[8];
    const float* dw2 = (const float*)d_in[9];
    const float* db2 = (const float*)d_in[10];
    const float* dw3 = (const float*)d_in[11];
    const float* db3 = (const float*)d_in[12];
    const float* cbk = (const float*)d_in[13];
    float* out = (float*)d_out;

    float *bufA, *bufB, *zb, *qb, *cnp, *l1p, *vqp;
    cudaGetSymbolAddress((void**)&bufA, g_bufA);
    cudaGetSymbolAddress((void**)&bufB, g_bufB);
    cudaGetSymbolAddress((void**)&zb,   g_z);
    cudaGetSymbolAddress((void**)&qb,   g_q);
    cudaGetSymbolAddress((void**)&cnp,  g_cn);
    cudaGetSymbolAddress((void**)&l1p,  g_l1p);
    cudaGetSymbolAddress((void**)&vqp,  g_vqp);

    // defensive: zero the whole output (poisoned to 0xAA by harness)
    cudaMemsetAsync(d_out, 0, (size_t)out_size * sizeof(float), 0);

    static_assert(sizeof(VqSmem) < 220 * 1024, "smem");
    cudaFuncSetAttribute(vq_k, cudaFuncAttributeMaxDynamicSharedMemorySize, (int)sizeof(VqSmem));

    dim3 blk(256);

    // encoder
    sgemm_k<1, 0><<<dim3(RB, 8), blk>>>(state, ew1, eb1, bufA,  56, 512, nullptr, nullptr);
    sgemm_k<1, 0><<<dim3(RB, 8), blk>>>(bufA,  ew2, eb2, bufB, 512, 512, nullptr, nullptr);
    sgemm_k<0, 0><<<dim3(RB, 4), blk>>>(bufB,  ew3, eb3, zb,   512, 256, nullptr, nullptr);

    // residual VQ
    cn_k<<<dim3(256), blk>>>(cbk, cnp);
    vq_k<<<dim3(RB), blk, sizeof(VqSmem)>>>(zb, cbk, cnp, qb, out + 1, vqp);

    // decoder (+ fused L1 partials on the last GEMM)
    sgemm_k<1, 0><<<dim3(RB, 8), blk>>>(qb,   dw1, db1, bufA, 256, 512, nullptr, nullptr);
    sgemm_k<1, 0><<<dim3(RB, 8), blk>>>(bufA, dw2, db2, bufB, 512, 512, nullptr, nullptr);
    sgemm_k<0, 1><<<dim3(RB, 1), blk>>>(bufB, dw3, db3, nullptr, 512, 56, state, l1p);

    final_k<<<1, 256>>>(l1p, vqp, out);
}

// round 2
// speedup vs baseline: 2.5865x; 2.5865x over previous
#include <cuda_runtime.h>
#include <cuda_bf16.h>
#include <math.h>

#define NROWS 131072
#define RB64  (NROWS/64)    // 2048  (encoder fp32 tiles)
#define RB128 (NROWS/128)   // 1024  (bf16 tiles)
#define MARGIN 1.0f
#define CAND_CAP 32

// ---------------- scratch (device globals; no allocation allowed) ----------------
__device__ float g_bufA[(size_t)NROWS * 512];
__device__ float g_bufB[(size_t)NROWS * 512];
__device__ float g_z   [(size_t)NROWS * 256];
__device__ float g_res [(size_t)NROWS * 256];
__device__ float g_q1  [(size_t)NROWS * 256];
__device__ __nv_bfloat16 g_qbf[(size_t)NROWS * 256];
__device__ __nv_bfloat16 g_cbh[2 * 1024 * 256];
__device__ __nv_bfloat16 g_wt1[512 * 256];
__device__ __nv_bfloat16 g_wt2[512 * 512];
__device__ __nv_bfloat16 g_wt3[56 * 512];
__device__ float g_cn  [2 * 1024];
__device__ float g_l1p [RB128];
__device__ float g_vqp [RB128];

// ---------------- small helpers ----------------
__device__ __forceinline__ unsigned smaddr(const void* p) {
    return (unsigned)__cvta_generic_to_shared(p);
}
__device__ __forceinline__ void cpa16(unsigned dst, const void* src, int sz) {
    asm volatile("cp.async.cg.shared.global [%0], [%1], 16, %2;\n"
                 :: "r"(dst), "l"(src), "r"(sz));
}
#define CP_COMMIT asm volatile("cp.async.commit_group;\n")
template<int N> __device__ __forceinline__ void cp_wait() {
    asm volatile("cp.async.wait_group %0;\n" :: "n"(N));
}
__device__ __forceinline__ void mma_bf16(float* c, const unsigned* a, unsigned b0, unsigned b1) {
    asm volatile(
        "mma.sync.aligned.m16n8k16.row.col.f32.bf16.bf16.f32 "
        "{%0,%1,%2,%3}, {%4,%5,%6,%7}, {%8,%9}, {%0,%1,%2,%3};\n"
        : "+f"(c[0]), "+f"(c[1]), "+f"(c[2]), "+f"(c[3])
        : "r"(a[0]), "r"(a[1]), "r"(a[2]), "r"(a[3]), "r"(b0), "r"(b1));
}
// order-preserving float<->uint maps for atomicMin on scores
__device__ __forceinline__ unsigned fford(float f) {
    unsigned u = __float_as_uint(f);
    return (u & 0x80000000u) ? ~u : (u | 0x80000000u);
}
__device__ __forceinline__ float iford(unsigned u) {
    return __uint_as_float((u & 0x80000000u) ? (u ^ 0x80000000u) : ~u);
}

// ================= fp32 SGEMM (encoder path, unchanged from round 1) =================
template<int RELU>
__global__ __launch_bounds__(256) void sgemm_k(
    const float* __restrict__ A, const float* __restrict__ B,
    const float* __restrict__ bias, float* __restrict__ C, int K, int M)
{
    __shared__ float As[64][17];
    __shared__ __align__(16) float Bs[16][64];

    const int tid = threadIdx.x;
    const int tx = tid & 15, ty = tid >> 4;
    const int row0 = blockIdx.x * 64;
    const int col0 = blockIdx.y * 64;

    float acc[4][4] = {};

    for (int k0 = 0; k0 < K; k0 += 16) {
        #pragma unroll
        for (int i = 0; i < 4; i++) {
            int r  = ty + 16 * i;
            int kk = k0 + tx;
            As[r][tx] = (kk < K) ? A[(size_t)(row0 + r) * K + kk] : 0.0f;
        }
        {
            int kk = k0 + ty;
            int c  = col0 + 4 * tx;
            float4 v = make_float4(0.f, 0.f, 0.f, 0.f);
            if (kk < K) v = *(const float4*)(B + (size_t)kk * M + c);
            *(float4*)(&Bs[ty][4 * tx]) = v;
        }
        __syncthreads();
        #pragma unroll
        for (int k = 0; k < 16; k++) {
            float4 b = *(const float4*)(&Bs[k][4 * tx]);
            float a0 = As[4 * ty + 0][k];
            float a1 = As[4 * ty + 1][k];
            float a2 = As[4 * ty + 2][k];
            float a3 = As[4 * ty + 3][k];
            acc[0][0] = fmaf(a0, b.x, acc[0][0]); acc[0][1] = fmaf(a0, b.y, acc[0][1]);
            acc[0][2] = fmaf(a0, b.z, acc[0][2]); acc[0][3] = fmaf(a0, b.w, acc[0][3]);
            acc[1][0] = fmaf(a1, b.x, acc[1][0]); acc[1][1] = fmaf(a1, b.y, acc[1][1]);
            acc[1][2] = fmaf(a1, b.z, acc[1][2]); acc[1][3] = fmaf(a1, b.w, acc[1][3]);
            acc[2][0] = fmaf(a2, b.x, acc[2][0]); acc[2][1] = fmaf(a2, b.y, acc[2][1]);
            acc[2][2] = fmaf(a2, b.z, acc[2][2]); acc[2][3] = fmaf(a2, b.w, acc[2][3]);
            acc[3][0] = fmaf(a3, b.x, acc[3][0]); acc[3][1] = fmaf(a3, b.y, acc[3][1]);
            acc[3][2] = fmaf(a3, b.z, acc[3][2]); acc[3][3] = fmaf(a3, b.w, acc[3][3]);
        }
        __syncthreads();
    }

    #pragma unroll
    for (int i = 0; i < 4; i++) {
        int r = row0 + 4 * ty + i;
        int c = col0 + 4 * tx;
        float4 o;
        o.x = acc[i][0] + bias[c + 0];
        o.y = acc[i][1] + bias[c + 1];
        o.z = acc[i][2] + bias[c + 2];
        o.w = acc[i][3] + bias[c + 3];
        if (RELU) {
            o.x = fmaxf(o.x, 0.f); o.y = fmaxf(o.y, 0.f);
            o.z = fmaxf(o.z, 0.f); o.w = fmaxf(o.w, 0.f);
        }
        *(float4*)(C + (size_t)r * M + c) = o;
    }
}

// ================= prep kernels =================
__global__ __launch_bounds__(256) void cn_k(const float* __restrict__ cb, float* __restrict__ cn)
{
    int w = (blockIdx.x * blockDim.x + threadIdx.x) >> 5;
    int lane = threadIdx.x & 31;
    if (w < 2048) {
        const float* c = cb + (size_t)w * 256;
        float s = 0.f;
        #pragma unroll
        for (int k = lane; k < 256; k += 32) s = fmaf(c[k], c[k], s);
        #pragma unroll
        for (int off = 16; off > 0; off >>= 1) s += __shfl_xor_sync(0xffffffff, s, off);
        if (lane == 0) cn[w] = 0.5f * s;
    }
}
__global__ __launch_bounds__(256) void cvt_k(const float* __restrict__ src,
                                             __nv_bfloat16* __restrict__ dst, int n)
{
    int i = blockIdx.x * 256 + threadIdx.x;
    if (i < n) dst[i] = __float2bfloat16(src[i]);
}
// W [K][M] fp32 -> BT [M][K] bf16
__global__ __launch_bounds__(256) void tr_k(const float* __restrict__ W,
                                            __nv_bfloat16* __restrict__ BT, int K, int M)
{
    int i = blockIdx.x * 256 + threadIdx.x;
    if (i < K * M) {
        int k = i / M, m = i % M;
        BT[(size_t)m * K + k] = __float2bfloat16(W[i]);
    }
}

// ================= bf16 HGEMM (decoder): C[rows,M] = A[rows,K] @ BT[M,K]^T =================
// 128x128 tile, 256 threads (8 warps in 4x2), k-chunk 64, 2-stage cp.async pipeline.
__device__ __forceinline__ void hfill(const __nv_bfloat16* __restrict__ A,
                                      const __nv_bfloat16* __restrict__ BT,
                                      unsigned As0, unsigned Bs0, int stage, int k0,
                                      int row0, int col0, int K, int M, int tid)
{
    #pragma unroll
    for (int i = 0; i < 4; i++) {
        int ch = tid + 256 * i;
        int r = ch >> 3, g = ch & 7;
        cpa16(As0 + (unsigned)(stage * 9216 + r * 72 + g * 8) * 2,
              A + (size_t)(row0 + r) * K + k0 + g * 8, 16);
    }
    #pragma unroll
    for (int i = 0; i < 4; i++) {
        int ch = tid + 256 * i;
        int r = ch >> 3, g = ch & 7;
        int br = col0 + r;
        int ok = (br < M);
        const __nv_bfloat16* src = BT + (size_t)(ok ? br : 0) * K + k0 + g * 8;
        cpa16(Bs0 + (unsigned)(stage * 9216 + r * 72 + g * 8) * 2, src, ok ? 16 : 0);
    }
}
__device__ __forceinline__ void hcompute(const __nv_bfloat16* As, const __nv_bfloat16* Bs,
                                         int stage, int wm, int wn, int lane,
                                         float acc[2][8][4])
{
    const int g = lane >> 2, q2 = (lane & 3) * 2;
    #pragma unroll
    for (int kk = 0; kk < 64; kk += 16) {
        unsigned a[2][4];
        #pragma unroll
        for (int mf = 0; mf < 2; mf++) {
            const __nv_bfloat16* p = As + stage * 9216 + (wm * 32 + mf * 16 + g) * 72;
            a[mf][0] = *(const unsigned*)(p + kk + q2);
            a[mf][1] = *(const unsigned*)(p + 8 * 72 + kk + q2);
            a[mf][2] = *(const unsigned*)(p + kk + 8 + q2);
            a[mf][3] = *(const unsigned*)(p + 8 * 72 + kk + 8 + q2);
        }
        #pragma unroll
        for (int nf = 0; nf < 8; nf++) {
            const __nv_bfloat16* bp = Bs + stage * 9216 + (wn * 64 + nf * 8 + g) * 72 + kk + q2;
            unsigned b0 = *(const unsigned*)bp;
            unsigned b1 = *(const unsigned*)(bp + 8);
            mma_bf16(acc[0][nf], a[0], b0, b1);
            mma_bf16(acc[1][nf], a[1], b0, b1);
        }
    }
}

template<int RELU, int L1EPI>
__global__ __launch_bounds__(256) void hgemm_k(
    const __nv_bfloat16* __restrict__ A, const __nv_bfloat16* __restrict__ BT,
    const float* __restrict__ bias, __nv_bfloat16* __restrict__ C, int K, int M,
    const float* __restrict__ Xref, float* __restrict__ part)
{
    extern __shared__ __align__(16) char sm[];
    __nv_bfloat16* As = (__nv_bfloat16*)sm;            // [2][128][72]
    __nv_bfloat16* Bs = As + 2 * 128 * 72;             // [2][128][72]
    float* red = (float*)(sm + 73728);

    const int tid = threadIdx.x;
    const int lane = tid & 31, wid = tid >> 5;
    const int wm = wid & 3, wn = wid >> 2;
    const int row0 = blockIdx.x * 128;
    const int col0 = blockIdx.y * 128;
    const unsigned As0 = smaddr(As), Bs0 = smaddr(Bs);

    float acc[2][8][4];
    #pragma unroll
    for (int a = 0; a < 2; a++)
        #pragma unroll
        for (int b = 0; b < 8; b++)
            #pragma unroll
            for (int c = 0; c < 4; c++) acc[a][b][c] = 0.f;

    const int nk = K >> 6;
    hfill(A, BT, As0, Bs0, 0, 0, row0, col0, K, M, tid);
    CP_COMMIT;
    for (int kc = 0; kc < nk; kc++) {
        if (kc + 1 < nk) {
            hfill(A, BT, As0, Bs0, (kc + 1) & 1, (kc + 1) * 64, row0, col0, K, M, tid);
            CP_COMMIT;
            cp_wait<1>();
        } else {
            cp_wait<0>();
        }
        __syncthreads();
        hcompute(As, Bs, kc & 1, wm, wn, lane, acc);
        __syncthreads();
    }

    const int g = lane >> 2, q2 = (lane & 3) * 2;
    if (!L1EPI) {
        #pragma unroll
        for (int mf = 0; mf < 2; mf++) {
            int r1 = row0 + wm * 32 + mf * 16 + g;
            #pragma unroll
            for (int nf = 0; nf < 8; nf++) {
                int cc = col0 + wn * 64 + nf * 8 + q2;
                float v0 = acc[mf][nf][0] + bias[cc];
                float v1 = acc[mf][nf][1] + bias[cc + 1];
                float v2 = acc[mf][nf][2] + bias[cc];
                float v3 = acc[mf][nf][3] + bias[cc + 1];
                if (RELU) {
                    v0 = fmaxf(v0, 0.f); v1 = fmaxf(v1, 0.f);
                    v2 = fmaxf(v2, 0.f); v3 = fmaxf(v3, 0.f);
                }
                __nv_bfloat162 h0; h0.x = __float2bfloat16(v0); h0.y = __float2bfloat16(v1);
                __nv_bfloat162 h1; h1.x = __float2bfloat16(v2); h1.y = __float2bfloat16(v3);
                *(__nv_bfloat162*)(C + (size_t)r1 * M + cc) = h0;
                *(__nv_bfloat162*)(C + (size_t)(r1 + 8) * M + cc) = h1;
            }
        }
    } else {
        float s = 0.f;
        #pragma unroll
        for (int mf = 0; mf < 2; mf++) {
            int r1 = row0 + wm * 32 + mf * 16 + g;
            #pragma unroll
            for (int nf = 0; nf < 8; nf++) {
                int cc = col0 + wn * 64 + nf * 8 + q2;
                #pragma unroll
                for (int e = 0; e < 4; e++) {
                    int c = cc + (e & 1);
                    int r = r1 + (e >= 2 ? 8 : 0);
                    if (c < M) {
                        float v = acc[mf][nf][e] + bias[c];
                        s += fabsf(Xref[(size_t)r * M + c] - v);
                    }
                }
            }
        }
        red[tid] = s;
        __syncthreads();
        #pragma unroll
        for (int off = 128; off > 0; off >>= 1) {
            if (tid < off) red[tid] += red[tid + off];
            __syncthreads();
        }
        if (tid == 0) part[blockIdx.x] = red[0];
    }
}

// ================= fused bf16 VQ: score (HMMA) + exact fp32 re-argmin + update =================
// CTA = 128 rows; loops 8 code tiles of 128 (K=256), margin-candidate rescue in fp32.
// smem layout (bytes):
//   As   : 0      .. 67584   bf16[128*264]
//   Bs   : 67584  .. 202752  bf16[2][128*264]
//   cand : 202752 .. 219136  int[128*32]
//   rowmin:219136 .. 219648  uint[128]
//   cnt  : 219648 .. 220160  int[128]
//   chosen:220160 .. 220672  int[128]
//   red  : 220672 .. 221696  float[256]
#define VQ_SMEM 221696

template<int Q>
__global__ __launch_bounds__(256) void vqscore_k(
    const float* __restrict__ rg, const __nv_bfloat16* __restrict__ cbh,
    const float* __restrict__ cbf, const float* __restrict__ cn,
    float* __restrict__ codes_out, float* __restrict__ res_out,
    float* __restrict__ q1buf, __nv_bfloat16* __restrict__ qbf,
    float* __restrict__ vqpart)
{
    extern __shared__ __align__(16) char sm[];
    __nv_bfloat16* As = (__nv_bfloat16*)sm;                    // [128][264]
    __nv_bfloat16* Bs = (__nv_bfloat16*)(sm + 67584);          // [2][128][264]
    int*      cand   = (int*)     (sm + 202752);
    unsigned* rowmin = (unsigned*)(sm + 219136);
    int*      cnt    = (int*)     (sm + 219648);
    int*      chosen = (int*)     (sm + 220160);
    float*    red    = (float*)   (sm + 220672);

    const int tid = threadIdx.x;
    const int lane = tid & 31, wid = tid >> 5;
    const int wm = wid & 3, wn = wid >> 2;
    const size_t row0 = (size_t)blockIdx.x * 128;
    const unsigned Bs0 = smaddr(Bs);
    const int g = lane >> 2, q2 = (lane & 3) * 2;

    if (tid < 128) { rowmin[tid] = 0xFFFFFFFFu; cnt[tid] = 0; }

    // load + convert A tile (128 x 256 fp32 -> bf16, padded stride 264)
    #pragma unroll
    for (int i = 0; i < 32; i++) {
        int e = tid + 256 * i;        // over 8192 float4 groups
        int r = e >> 6, c4 = e & 63;
        float4 v = *(const float4*)(rg + (row0 + r) * 256 + 4 * c4);
        __nv_bfloat162 h0; h0.x = __float2bfloat16(v.x); h0.y = __float2bfloat16(v.y);
        __nv_bfloat162 h1; h1.x = __float2bfloat16(v.z); h1.y = __float2bfloat16(v.w);
        *(__nv_bfloat162*)(As + r * 264 + 4 * c4) = h0;
        *(__nv_bfloat162*)(As + r * 264 + 4 * c4 + 2) = h1;
    }
    __syncthreads();

    // prefetch B tile 0
    #pragma unroll
    for (int i = 0; i < 16; i++) {
        int ch = tid + 256 * i;
        int r = ch >> 5, gg = ch & 31;
        cpa16(Bs0 + (unsigned)(r * 264 + gg * 8) * 2,
              cbh + (size_t)r * 256 + gg * 8, 16);
    }
    CP_COMMIT;

    for (int t = 0; t < 8; t++) {
        if (t < 7) {
            int st = (t + 1) & 1;
            #pragma unroll
            for (int i = 0; i < 16; i++) {
                int ch = tid + 256 * i;
                int r = ch >> 5, gg = ch & 31;
                cpa16(Bs0 + (unsigned)(st * 33792 + r * 264 + gg * 8) * 2,
                      cbh + (size_t)((t + 1) * 128 + r) * 256 + gg * 8, 16);
            }
            CP_COMMIT;
            cp_wait<1>();
        } else {
            cp_wait<0>();
        }
        __syncthreads();

        float acc[2][8][4];
        #pragma unroll
        for (int a = 0; a < 2; a++)
            #pragma unroll
            for (int b = 0; b < 8; b++)
                #pragma unroll
                for (int c = 0; c < 4; c++) acc[a][b][c] = 0.f;

        const __nv_bfloat16* Bst = Bs + (t & 1) * 33792;
        #pragma unroll
        for (int kk = 0; kk < 256; kk += 16) {
            unsigned a[2][4];
            #pragma unroll
            for (int mf = 0; mf < 2; mf++) {
                const __nv_bfloat16* p = As + (wm * 32 + mf * 16 + g) * 264;
                a[mf][0] = *(const unsigned*)(p + kk + q2);
                a[mf][1] = *(const unsigned*)(p + 8 * 264 + kk + q2);
                a[mf][2] = *(const unsigned*)(p + kk + 8 + q2);
                a[mf][3] = *(const unsigned*)(p + 8 * 264 + kk + 8 + q2);
            }
            #pragma unroll
            for (int nf = 0; nf < 8; nf++) {
                const __nv_bfloat16* bp = Bst + (wn * 64 + nf * 8 + g) * 264 + kk + q2;
                unsigned b0 = *(const unsigned*)bp;
                unsigned b1 = *(const unsigned*)(bp + 8);
                mma_bf16(acc[0][nf], a[0], b0, b1);
                mma_bf16(acc[1][nf], a[1], b0, b1);
            }
        }

        // epilogue: scores s = cn - dot; per-thread min per row, then atomicMin
        #pragma unroll
        for (int mf = 0; mf < 2; mf++) {
            int r1 = wm * 32 + mf * 16 + g;
            float m1 = 1e30f, m2 = 1e30f;
            #pragma unroll
            for (int nf = 0; nf < 8; nf++) {
                int cl = wn * 64 + nf * 8 + q2;
                float cn0 = __ldg(cn + t * 128 + cl);
                float cn1 = __ldg(cn + t * 128 + cl + 1);
                float s0 = cn0 - acc[mf][nf][0];
                float s1 = cn1 - acc[mf][nf][1];
                float s2 = cn0 - acc[mf][nf][2];
                float s3 = cn1 - acc[mf][nf][3];
                acc[mf][nf][0] = s0; acc[mf][nf][1] = s1;
                acc[mf][nf][2] = s2; acc[mf][nf][3] = s3;
                m1 = fminf(m1, fminf(s0, s1));
                m2 = fminf(m2, fminf(s2, s3));
            }
            atomicMin(&rowmin[r1], fford(m1));
            atomicMin(&rowmin[r1 + 8], fford(m2));
        }
        __syncthreads();
        // candidate push (threshold = current row min + margin; superset of final)
        #pragma unroll
        for (int mf = 0; mf < 2; mf++) {
            int r1 = wm * 32 + mf * 16 + g;
            float thr1 = iford(rowmin[r1]) + MARGIN;
            float thr2 = iford(rowmin[r1 + 8]) + MARGIN;
            #pragma unroll
            for (int nf = 0; nf < 8; nf++) {
                int code = t * 128 + wn * 64 + nf * 8 + q2;
                #pragma unroll
                for (int e = 0; e < 4; e++) {
                    float s = acc[mf][nf][e];
                    int r = (e >= 2) ? (r1 + 8) : r1;
                    float thr = (e >= 2) ? thr2 : thr1;
                    if (s <= thr) {
                        int p = atomicAdd(&cnt[r], 1);
                        if (p < CAND_CAP) cand[r * CAND_CAP + p] = code + (e & 1);
                    }
                }
            }
        }
        __syncthreads();
    }

    // ---- exact fp32 rescue: one warp per row, 16 rows per warp ----
    for (int j = 0; j < 16; j++) {
        int row = wid + 8 * j;
        const float* rp = rg + (row0 + row) * 256 + lane * 8;
        float4 u = *(const float4*)rp;
        float4 v = *(const float4*)(rp + 4);
        float rr[8] = {u.x, u.y, u.z, u.w, v.x, v.y, v.z, v.w};
        int cv = cnt[row];
        float bv = 1e30f; int bc = 0;
        if (cv <= CAND_CAP) {
            for (int i = 0; i < cv; i++) {
                int c = cand[row * CAND_CAP + i];
                const float* cp = cbf + (size_t)c * 256 + lane * 8;
                float d = 0.f;
                #pragma unroll
                for (int e = 0; e < 8; e++) d = fmaf(rr[e], __ldg(cp + e), d);
                #pragma unroll
                for (int off = 16; off > 0; off >>= 1) d += __shfl_xor_sync(0xffffffff, d, off);
                float s = __ldg(cn + c) - d;
                if (s < bv || (s == bv && c < bc)) { bv = s; bc = c; }
            }
        } else {   // overflow fallback: full exact scan
            for (int c = 0; c < 1024; c++) {
                const float* cp = cbf + (size_t)c * 256 + lane * 8;
                float d = 0.f;
                #pragma unroll
                for (int e = 0; e < 8; e++) d = fmaf(rr[e], __ldg(cp + e), d);
                #pragma unroll
                for (int off = 16; off > 0; off >>= 1) d += __shfl_xor_sync(0xffffffff, d, off);
                float s = __ldg(cn + c) - d;
                if (s < bv || (s == bv && c < bc)) { bv = s; bc = c; }
            }
        }
        if (lane == 0) {
            chosen[row] = bc;
            codes_out[(row0 + row) * 2 + Q] = (float)bc;
        }
    }
    __syncthreads();

    // ---- update: residual / q accumulation / commitment loss (exact fp32) ----
    float vac = 0.f;
    #pragma unroll
    for (int i = 0; i < 32; i++) {
        int e = tid + 256 * i;
        int r = e >> 6, c4 = e & 63;
        int c = chosen[r];
        size_t off = (row0 + r) * 256 + 4 * c4;
        float4 cvv = *(const float4*)(cbf + (size_t)c * 256 + 4 * c4);
        float4 zv  = *(const float4*)(rg + off);
        float4 dv = make_float4(zv.x - cvv.x, zv.y - cvv.y, zv.z - cvv.z, zv.w - cvv.w);
        vac += dv.x * dv.x + dv.y * dv.y + dv.z * dv.z + dv.w * dv.w;
        if (Q == 0) {
            *(float4*)(res_out + off) = dv;
            *(float4*)(q1buf + off) = cvv;
        } else {
            float4 q1v = *(const float4*)(q1buf + off);
            float4 sv = make_float4(q1v.x + cvv.x, q1v.y + cvv.y, q1v.z + cvv.z, q1v.w + cvv.w);
            __nv_bfloat162 h0; h0.x = __float2bfloat16(sv.x); h0.y = __float2bfloat16(sv.y);
            __nv_bfloat162 h1; h1.x = __float2bfloat16(sv.z); h1.y = __float2bfloat16(sv.w);
            *(__nv_bfloat162*)(qbf + off) = h0;
            *(__nv_bfloat162*)(qbf + off + 2) = h1;
        }
    }
    red[tid] = vac;
    __syncthreads();
    #pragma unroll
    for (int off = 128; off > 0; off >>= 1) {
        if (tid < off) red[tid] += red[tid + off];
        __syncthreads();
    }
    if (tid == 0) {
        if (Q == 0) vqpart[blockIdx.x] = red[0];
        else        vqpart[blockIdx.x] += red[0];
    }
}

// ================= final deterministic loss combine =================
__global__ __launch_bounds__(256) void final_k(
    const float* __restrict__ l1p, const float* __restrict__ vqp, float* __restrict__ out)
{
    __shared__ float sa[256], sb[256];
    float a = 0.f, b = 0.f;
    for (int i = threadIdx.x; i < RB128; i += 256) { a += l1p[i]; b += vqp[i]; }
    sa[threadIdx.x] = a; sb[threadIdx.x] = b;
    __syncthreads();
    #pragma unroll
    for (int off = 128; off > 0; off >>= 1) {
        if (threadIdx.x < off) {
            sa[threadIdx.x] += sa[threadIdx.x + off];
            sb[threadIdx.x] += sb[threadIdx.x + off];
        }
        __syncthreads();
    }
    if (threadIdx.x == 0) {
        float enc_loss = sa[0] / (131072.0f * 56.0f);
        float vq_loss  = sb[0] / (131072.0f * 256.0f);
        out[0] = enc_loss + 5.0f * vq_loss;
    }
}

// ================= launch =================
extern "C" void kernel_launch(void* const* d_in, const int* in_sizes, int n_in,
                              void* d_out, int out_size)
{
    const float* state = (const float*)d_in[0];
    const float* ew1 = (const float*)d_in[1];
    const float* eb1 = (const float*)d_in[2];
    const float* ew2 = (const float*)d_in[3];
    const float* eb2 = (const float*)d_in[4];
    const float* ew3 = (const float*)d_in[5];
    const float* eb3 = (const float*)d_in[6];
    const float* dw1 = (const float*)d_in[7];
    const float* db1 = (const float*)d_in[8];
    const float* dw2 = (const float*)d_in[9];
    const float* db2 = (const float*)d_in[10];
    const float* dw3 = (const float*)d_in[11];
    const float* db3 = (const float*)d_in[12];
    const float* cbk = (const float*)d_in[13];
    float* out = (float*)d_out;

    float *bufA, *bufB, *zb, *resb, *q1b, *cnp, *l1p, *vqp;
    __nv_bfloat16 *qbf, *cbh, *wt1, *wt2, *wt3;
    cudaGetSymbolAddress((void**)&bufA, g_bufA);
    cudaGetSymbolAddress((void**)&bufB, g_bufB);
    cudaGetSymbolAddress((void**)&zb,   g_z);
    cudaGetSymbolAddress((void**)&resb, g_res);
    cudaGetSymbolAddress((void**)&q1b,  g_q1);
    cudaGetSymbolAddress((void**)&qbf,  g_qbf);
    cudaGetSymbolAddress((void**)&cbh,  g_cbh);
    cudaGetSymbolAddress((void**)&wt1,  g_wt1);
    cudaGetSymbolAddress((void**)&wt2,  g_wt2);
    cudaGetSymbolAddress((void**)&wt3,  g_wt3);
    cudaGetSymbolAddress((void**)&cnp,  g_cn);
    cudaGetSymbolAddress((void**)&l1p,  g_l1p);
    cudaGetSymbolAddress((void**)&vqp,  g_vqp);

    cudaMemsetAsync(d_out, 0, (size_t)out_size * sizeof(float), 0);

    cudaFuncSetAttribute(vqscore_k<0>, cudaFuncAttributeMaxDynamicSharedMemorySize, VQ_SMEM);
    cudaFuncSetAttribute(vqscore_k<1>, cudaFuncAttributeMaxDynamicSharedMemorySize, VQ_SMEM);
    cudaFuncSetAttribute(hgemm_k<1,0>, cudaFuncAttributeMaxDynamicSharedMemorySize, 74752);
    cudaFuncSetAttribute(hgemm_k<0,1>, cudaFuncAttributeMaxDynamicSharedMemorySize, 74752);

    dim3 blk(256);

    // prep: codebook bf16, half-norms, transposed bf16 decoder weights
    cn_k<<<256, blk>>>(cbk, cnp);
    cvt_k<<<(2*1024*256 + 255)/256, blk>>>(cbk, cbh, 2*1024*256);
    tr_k<<<(256*512 + 255)/256, blk>>>(dw1, wt1, 256, 512);
    tr_k<<<(512*512 + 255)/256, blk>>>(dw2, wt2, 512, 512);
    tr_k<<<(512*56  + 255)/256, blk>>>(dw3, wt3, 512, 56);

    // encoder (exact fp32 — defines z and therefore the codes)
    sgemm_k<1><<<dim3(RB64, 8), blk>>>(state, ew1, eb1, bufA,  56, 512);
    sgemm_k<1><<<dim3(RB64, 8), blk>>>(bufA,  ew2, eb2, bufB, 512, 512);
    sgemm_k<0><<<dim3(RB64, 4), blk>>>(bufB,  ew3, eb3, zb,   512, 256);

    // residual VQ (bf16 HMMA scoring + exact fp32 re-argmin)
    vqscore_k<0><<<RB128, blk, VQ_SMEM>>>(zb, cbh, cbk, cnp,
                                          out + 1, resb, q1b, nullptr, vqp);
    vqscore_k<1><<<RB128, blk, VQ_SMEM>>>(resb, cbh + 1024*256, cbk + 1024*256, cnp + 1024,
                                          out + 1, nullptr, q1b, qbf, vqp);

    // decoder (bf16 HMMA; only affects the scalar mean -> precision-safe)
    hgemm_k<1,0><<<dim3(RB128, 4), blk, 74752>>>(qbf, wt1, db1,
                                                 (__nv_bfloat16*)bufA, 256, 512, nullptr, nullptr);
    hgemm_k<1,0><<<dim3(RB128, 4), blk, 74752>>>((__nv_bfloat16*)bufA, wt2, db2,
                                                 (__nv_bfloat16*)bufB, 512, 512, nullptr, nullptr);
    hgemm_k<0,1><<<dim3(RB128, 1), blk, 74752>>>((__nv_bfloat16*)bufB, wt3, db3,
                                                 nullptr, 512, 56, state, l1p);

    final_k<<<1, 256>>>(l1p, vqp, out);
}